// round 4
// baseline (speedup 1.0000x reference)
#include <cuda_runtime.h>

#define BATCH   128
#define NANCH   8732
#define NCLS    21
#define NLOG    25
#define MAXOUT  5
#define CONF    0.5f
#define DEC_T   128
#define NMS_T   256
#define CAP     2048

// Candidate lists (device globals; zero-initialized at module load).
// g_cnt is restored to zero by nms_kernel every launch -> replay-consistent.
__device__ int                 g_cnt[BATCH];
__device__ float4              g_cbox[BATCH * NANCH];
__device__ unsigned long long  g_ckey[BATCH * NANCH];
__device__ float               g_ccls[BATCH * NANCH];

// ---------------------------------------------------------------------------
// Decode + softmax-max/argmax + candidate compaction.
// ---------------------------------------------------------------------------
__global__ void __launch_bounds__(DEC_T)
decode_kernel(const float* __restrict__ logits, const float* __restrict__ db) {
    __shared__ float tile[DEC_T * NLOG];
    const int NV = DEC_T * NLOG / 4;                       // 800 float4

    long long base = (long long)blockIdx.x * DEC_T;
    const float4* __restrict__ src = (const float4*)(logits + base * NLOG);
    float4* dst = (float4*)tile;

    float4 v[7];
    int tid = threadIdx.x;
#pragma unroll
    for (int k = 0; k < 7; k++) {
        int i = tid + k * DEC_T;
        if (i < NV) v[k] = src[i];
    }
#pragma unroll
    for (int k = 0; k < 7; k++) {
        int i = tid + k * DEC_T;
        if (i < NV) dst[i] = v[k];
    }
    __syncthreads();

    int gid = (int)base + tid;
    const float* L = tile + tid * NLOG;

    float best = L[4];
    int   bi   = 0;
#pragma unroll
    for (int c = 1; c < NCLS; c++) {
        float vv = L[4 + c];
        if (vv > best) { best = vv; bi = c; }
    }
    float sum = 0.f;
#pragma unroll
    for (int c = 0; c < NCLS; c++) sum += __expf(L[4 + c] - best);
    float score = 1.0f / sum;

    if (bi != 0 && score > CONF) {
        int b = gid / NANCH;
        int n = gid % NANCH;
        float4 d = ((const float4*)db)[n];
        float cy = 0.5f * (d.z + d.x);
        float cx = 0.5f * (d.w + d.y);
        float h  = d.z - d.x;
        float w  = d.w - d.y;
        float ncy = L[0] * h + cy;
        float ncx = L[1] * w + cx;
        float nh  = __expf(L[2]) * h;
        float nw  = __expf(L[3]) * w;
        float4 box;
        box.x = fminf(fmaxf(ncy - 0.5f * nh, 0.f), 1.f);
        box.y = fminf(fmaxf(ncx - 0.5f * nw, 0.f), 1.f);
        box.z = fminf(fmaxf(ncy + 0.5f * nh, 0.f), 1.f);
        box.w = fminf(fmaxf(ncx + 0.5f * nw, 0.f), 1.f);

        int slot = atomicAdd(&g_cnt[b], 1);
        size_t o = (size_t)b * NANCH + slot;
        unsigned hi = __float_as_uint(score) | 0x80000000u;
        unsigned lo = ((unsigned)(NANCH - n) << 14) | (unsigned)slot;
        g_ckey[o] = ((unsigned long long)hi << 32) | lo;
        g_cbox[o] = box;
        g_ccls[o] = (float)bi;
    }
    cudaTriggerProgrammaticLaunchCompletion();
}

// ---------------------------------------------------------------------------
// NMS: 256 threads stage candidates to smem (1 barrier), then warp 0 runs the
// whole sequential select/suppress loop barrier-free with fused
// suppress+argmax (each lane owns its stripe of candidates).
// ---------------------------------------------------------------------------
__global__ void __launch_bounds__(NMS_T)
nms_kernel(float* __restrict__ out) {
    __shared__ unsigned long long s_key[CAP];
    __shared__ float4             s_box[CAP];
    __shared__ float              s_cls[CAP];

    cudaGridDependencySynchronize();   // PDL: wait for decode results

    int b   = blockIdx.x;
    int tid = threadIdx.x;
    int M   = g_cnt[b];
    size_t base = (size_t)b * NANCH;
    bool fits = (M <= CAP);

    if (fits) {
        for (int i = tid; i < M; i += NMS_T) {
            s_key[i] = g_ckey[base + i];
            s_box[i] = g_cbox[base + i];
            s_cls[i] = g_ccls[base + i];
        }
    }
    __syncthreads();                   // everyone has read g_cnt[b]
    if (tid == 0) g_cnt[b] = 0;        // reset for next replay

    if (tid >= 32) return;             // warp 0 only from here on

    unsigned long long* keys  = fits ? s_key : (g_ckey + base);
    const float4*       boxes = fits ? s_box : (g_cbox + base);
    const float*        cls   = fits ? s_cls : (g_ccls + base);

    // initial warp argmax
    unsigned long long bp = 0ull;
    for (int i = tid; i < M; i += 32) {
        unsigned long long k = keys[i];
        if (k > bp) bp = k;
    }
#pragma unroll
    for (int off = 16; off > 0; off >>= 1) {
        unsigned long long o = __shfl_xor_sync(0xffffffffu, bp, off);
        if (o > bp) bp = o;
    }

    float* ob = out + (size_t)b * MAXOUT * 6;
    for (int t = 0; t < MAXOUT; t++) {
        if (bp == 0ull) {
            if (tid == 0) {
                for (int tt = t; tt < MAXOUT; tt++) {
                    float* o = ob + tt * 6;
                    o[0] = o[1] = o[2] = o[3] = o[4] = o[5] = 0.f;
                }
            }
            return;
        }
        int   pos = (int)(bp & 0x3FFFull);
        float sc  = __uint_as_float((unsigned)(bp >> 32) & 0x7FFFFFFFu);
        float4 B  = boxes[pos];
        if (tid == 0) {
            float* o = ob + t * 6;
            o[0] = B.x; o[1] = B.y; o[2] = B.z; o[3] = B.w;
            o[4] = cls[pos]; o[5] = sc;
        }
        if (t == MAXOUT - 1) return;

        // fused suppression + next argmax (each lane owns its stripe)
        float a1 = (B.z - B.x) * (B.w - B.y);
        bp = 0ull;
        for (int i = tid; i < M; i += 32) {
            unsigned long long k = keys[i];
            if (!k) continue;
            float4 C = boxes[i];
            float ty  = fmaxf(B.x, C.x);
            float tx  = fmaxf(B.y, C.y);
            float by  = fminf(B.z, C.z);
            float bxr = fminf(B.w, C.w);
            float hh  = fmaxf(by - ty, 0.f);
            float ww  = fmaxf(bxr - tx, 0.f);
            float inter = hh * ww;
            float a2 = (C.z - C.x) * (C.w - C.y);
            float iou = inter / (a1 + a2 - inter + 1e-12f);
            if (iou > 0.5f) keys[i] = 0ull;
            else if (k > bp) bp = k;
        }
#pragma unroll
        for (int off = 16; off > 0; off >>= 1) {
            unsigned long long o = __shfl_xor_sync(0xffffffffu, bp, off);
            if (o > bp) bp = o;
        }
    }
}

// ---------------------------------------------------------------------------
extern "C" void kernel_launch(void* const* d_in, const int* in_sizes, int n_in,
                              void* d_out, int out_size) {
    const float* logits = (const float*)d_in[0];   // [128, 8732, 25]
    const float* db     = (const float*)d_in[1];   // [8732, 4]
    float*       out    = (float*)d_out;           // [128, 5, 6]

    decode_kernel<<<BATCH * NANCH / DEC_T, DEC_T>>>(logits, db);

    // PDL launch: nms may begin while decode drains; it synchronizes on the
    // grid dependency before touching decode output.
    cudaLaunchConfig_t cfg = {};
    cfg.gridDim  = dim3(BATCH);
    cfg.blockDim = dim3(NMS_T);
    cfg.dynamicSmemBytes = 0;
    cfg.stream = 0;
    cudaLaunchAttribute attr[1];
    attr[0].id = cudaLaunchAttributeProgrammaticStreamSerialization;
    attr[0].val.programmaticStreamSerializationAllowed = 1;
    cfg.attrs = attr;
    cfg.numAttrs = 1;
    cudaLaunchKernelEx(&cfg, nms_kernel, out);
}